// round 7
// baseline (speedup 1.0000x reference)
#include <cuda_runtime.h>
#include <math.h>

#define BATCH 4
#define SEQ   2048
#define DM    768
#define NH    12
#define HD    64
#define MTOT  (BATCH*SEQ)
#define N1    (3*DM)

// Scratch (static device arrays; no allocations allowed)
__device__ float g_q [BATCH*NH*SEQ*HD];   // [B,H,N,HD] tf32-rounded, hd PAIR-PERMUTED, PRE-SCALED by 1/8
__device__ float g_k [BATCH*NH*SEQ*HD];   // [B,H,N,HD] tf32-rounded, hd PAIR-PERMUTED
__device__ float g_v [BATCH*NH*SEQ*HD];   // [B,H,N,HD] tf32-rounded, natural layout
__device__ float g_ao[MTOT*DM];           // [B,N,H*HD] tf32-rounded
__device__ float g_xr[MTOT*DM];           // tf32-rounded x
__device__ float g_wq[DM*N1];             // tf32-rounded w_qkv
__device__ float g_wp[DM*DM];             // tf32-rounded w_proj

__device__ __forceinline__ unsigned f2tf(float f) {
    unsigned u;
    asm("cvt.rna.tf32.f32 %0, %1;" : "=r"(u) : "f"(f));
    return u;
}

__device__ __forceinline__ void mma_tf32(
    float &d0, float &d1, float &d2, float &d3,
    unsigned a0, unsigned a1, unsigned a2, unsigned a3,
    unsigned b0, unsigned b1)
{
    asm volatile(
        "mma.sync.aligned.m16n8k8.row.col.f32.tf32.tf32.f32 "
        "{%0,%1,%2,%3},{%4,%5,%6,%7},{%8,%9},{%0,%1,%2,%3};"
        : "+f"(d0), "+f"(d1), "+f"(d2), "+f"(d3)
        : "r"(a0), "r"(a1), "r"(a2), "r"(a3), "r"(b0), "r"(b1));
}

__device__ __forceinline__ void cp16(void* smem, const void* g) {
    unsigned a = (unsigned)__cvta_generic_to_shared(smem);
    asm volatile("cp.async.cg.shared.global [%0], [%1], 16;" :: "r"(a), "l"(g));
}

// non-hoistable gmem float2 load (keeps Q streaming, prevents 64-reg blowup)
__device__ __forceinline__ float2 ldg_f2v(const float* p) {
    float2 v;
    asm volatile("ld.global.nc.v2.f32 {%0,%1}, [%2];" : "=f"(v.x), "=f"(v.y) : "l"(p));
    return v;
}

// ---------------------------------------------------------------------------
// Prepass: round x, w_qkv, w_proj to tf32 once.
// ---------------------------------------------------------------------------
__global__ void round_prepass(const float* __restrict__ x,
                              const float* __restrict__ wq,
                              const float* __restrict__ wp)
{
    const int i      = blockIdx.x * blockDim.x + threadIdx.x;
    const int stride = gridDim.x * blockDim.x;
#pragma unroll 1
    for (int j = i; j < MTOT * DM / 4; j += stride) {
        float4 v = ((const float4*)x)[j];
        uint4 u; u.x = f2tf(v.x); u.y = f2tf(v.y); u.z = f2tf(v.z); u.w = f2tf(v.w);
        ((uint4*)g_xr)[j] = u;
    }
#pragma unroll 1
    for (int j = i; j < DM * N1 / 4; j += stride) {
        float4 v = ((const float4*)wq)[j];
        uint4 u; u.x = f2tf(v.x); u.y = f2tf(v.y); u.z = f2tf(v.z); u.w = f2tf(v.w);
        ((uint4*)g_wq)[j] = u;
    }
#pragma unroll 1
    for (int j = i; j < DM * DM / 4; j += stride) {
        float4 v = ((const float4*)wp)[j];
        uint4 u; u.x = f2tf(v.x); u.y = f2tf(v.y); u.z = f2tf(v.z); u.w = f2tf(v.w);
        ((uint4*)g_wp)[j] = u;
    }
}

// ---------------------------------------------------------------------------
// tf32 MMA GEMM, cp.async double-buffered (unchanged from R5/R6).
// ---------------------------------------------------------------------------
#define AS_WORDS (128 * 36)
#define BS_WORDS (32 * 136)
#define GEMM_SMEM_BYTES (2 * (AS_WORDS + BS_WORDS) * 4)   // 71680

#define GEMM_PIPE_BODY(LDB, A_PTR, W_PTR)                                     \
    extern __shared__ unsigned dsm[];                                         \
    const int tid  = threadIdx.x;                                             \
    const int w    = tid >> 5;                                                \
    const int lane = tid & 31;                                                \
    const int g    = lane >> 2;                                               \
    const int t    = lane & 3;                                                \
    const int wm   = w & 1;                                                   \
    const int wn   = w >> 1;                                                  \
    const int m0   = blockIdx.y << 7;                                         \
    const int n0   = blockIdx.x << 7;                                         \
    float acc[4][4][4];                                                       \
    _Pragma("unroll")                                                         \
    for (int mt = 0; mt < 4; mt++)                                            \
        _Pragma("unroll")                                                     \
        for (int nt = 0; nt < 4; nt++)                                        \
            _Pragma("unroll")                                                 \
            for (int c = 0; c < 4; c++) acc[mt][nt][c] = 0.f;                 \
    {                                                                         \
        unsigned* As = dsm;                                                   \
        unsigned* Bs = dsm + 2 * AS_WORDS;                                    \
        _Pragma("unroll")                                                     \
        for (int i = 0; i < 4; i++) {                                         \
            int f = i * 256 + tid;                                            \
            int r = f >> 3;                                                   \
            int c = (f & 7) << 2;                                             \
            cp16(&As[r * 36 + c], (A_PTR) + (size_t)(m0 + r) * DM + c);       \
            int k = f >> 5;                                                   \
            int n = (f & 31) << 2;                                            \
            cp16(&Bs[k * 136 + n], (W_PTR) + (size_t)k * (LDB) + n0 + n);     \
        }                                                                     \
        asm volatile("cp.async.commit_group;");                               \
    }                                                                         \
    for (int it = 0; it < DM / 32; it++) {                                    \
        const int cur = it & 1;                                               \
        unsigned* As = dsm + cur * AS_WORDS;                                  \
        unsigned* Bs = dsm + 2 * AS_WORDS + cur * BS_WORDS;                   \
        asm volatile("cp.async.wait_group 0;");                               \
        __syncthreads();                                                      \
        if (it + 1 < DM / 32) {                                               \
            const int nxt = (it + 1) & 1;                                     \
            const int k0n = (it + 1) * 32;                                    \
            unsigned* An = dsm + nxt * AS_WORDS;                              \
            unsigned* Bn = dsm + 2 * AS_WORDS + nxt * BS_WORDS;               \
            _Pragma("unroll")                                                 \
            for (int i = 0; i < 4; i++) {                                     \
                int f = i * 256 + tid;                                        \
                int r = f >> 3;                                               \
                int c = (f & 7) << 2;                                         \
                cp16(&An[r * 36 + c], (A_PTR) + (size_t)(m0 + r) * DM + k0n + c); \
                int k = f >> 5;                                               \
                int n = (f & 31) << 2;                                        \
                cp16(&Bn[k * 136 + n], (W_PTR) + (size_t)(k0n + k) * (LDB) + n0 + n); \
            }                                                                 \
            asm volatile("cp.async.commit_group;");                           \
        }                                                                     \
        _Pragma("unroll")                                                     \
        for (int kk = 0; kk < 4; kk++) {                                      \
            unsigned a[4][4], b[4][2];                                        \
            _Pragma("unroll")                                                 \
            for (int mt = 0; mt < 4; mt++) {                                  \
                int row = wm * 64 + mt * 16;                                  \
                a[mt][0] = As[(row + g) * 36 + kk * 8 + t];                   \
                a[mt][1] = As[(row + 8 + g) * 36 + kk * 8 + t];               \
                a[mt][2] = As[(row + g) * 36 + kk * 8 + t + 4];               \
                a[mt][3] = As[(row + 8 + g) * 36 + kk * 8 + t + 4];           \
            }                                                                 \
            _Pragma("unroll")                                                 \
            for (int nt = 0; nt < 4; nt++) {                                  \
                int cn = wn * 32 + nt * 8 + g;                                \
                b[nt][0] = Bs[(kk * 8 + t) * 136 + cn];                       \
                b[nt][1] = Bs[(kk * 8 + t + 4) * 136 + cn];                   \
            }                                                                 \
            _Pragma("unroll")                                                 \
            for (int mt = 0; mt < 4; mt++)                                    \
                _Pragma("unroll")                                             \
                for (int nt = 0; nt < 4; nt++)                                \
                    mma_tf32(acc[mt][nt][0], acc[mt][nt][1],                  \
                             acc[mt][nt][2], acc[mt][nt][3],                  \
                             a[mt][0], a[mt][1], a[mt][2], a[mt][3],          \
                             b[nt][0], b[nt][1]);                             \
        }                                                                     \
        __syncthreads();                                                      \
    }

// GEMM1: qkv -> g_q/g_k/g_v. Q/K pair-permuted; Q additionally pre-scaled 1/8.
__global__ __launch_bounds__(256, 2) void gemm_qkv_tf32(
    const float* __restrict__ bias)
{
    GEMM_PIPE_BODY(N1, g_xr, g_wq)

#pragma unroll
    for (int mt = 0; mt < 4; mt++) {
        int r_lo = m0 + wm * 64 + mt * 16 + g;
        int bat0 = r_lo >> 11,       n_0 = r_lo & (SEQ - 1);
        int bat1 = (r_lo + 8) >> 11, n_1 = (r_lo + 8) & (SEQ - 1);
#pragma unroll
        for (int nt = 0; nt < 4; nt++) {
            int col = n0 + wn * 32 + nt * 8 + 2 * t;
            int seg = col / DM;
            int cc  = col - seg * DM;
            int h   = cc >> 6;
            int hd  = cc & 63;
            float b0 = bias[col], b1 = bias[col + 1];
            if (seg == 2) {
                float2 v0;
                v0.x = __uint_as_float(f2tf(acc[mt][nt][0] + b0));
                v0.y = __uint_as_float(f2tf(acc[mt][nt][1] + b1));
                *(float2*)&g_v[((size_t)(bat0 * NH + h) * SEQ + n_0) * HD + hd] = v0;
                float2 v1;
                v1.x = __uint_as_float(f2tf(acc[mt][nt][2] + b0));
                v1.y = __uint_as_float(f2tf(acc[mt][nt][3] + b1));
                *(float2*)&g_v[((size_t)(bat1 * NH + h) * SEQ + n_1) * HD + hd] = v1;
            } else {
                float* dst = (seg == 0) ? g_q : g_k;
                float sc   = (seg == 0) ? 0.125f : 1.0f;   // exact pow-2 fold
                int hdp0 = (hd & 56) | (2 * (hd & 3) + ((hd >> 2) & 1));
                int hd1  = hd + 1;
                int hdp1 = (hd1 & 56) | (2 * (hd1 & 3) + ((hd1 >> 2) & 1));
                size_t base0 = ((size_t)(bat0 * NH + h) * SEQ + n_0) * HD;
                size_t base1 = ((size_t)(bat1 * NH + h) * SEQ + n_1) * HD;
                dst[base0 + hdp0] = __uint_as_float(f2tf(acc[mt][nt][0] + b0)) * sc;
                dst[base0 + hdp1] = __uint_as_float(f2tf(acc[mt][nt][1] + b1)) * sc;
                dst[base1 + hdp0] = __uint_as_float(f2tf(acc[mt][nt][2] + b0)) * sc;
                dst[base1 + hdp1] = __uint_as_float(f2tf(acc[mt][nt][3] + b1)) * sc;
            }
        }
    }
}

// GEMM2: out = g_ao @ w_proj + b_proj
__global__ __launch_bounds__(256, 2) void gemm_proj_tf32(
    const float* __restrict__ bias, float* __restrict__ OUT)
{
    GEMM_PIPE_BODY(DM, g_ao, g_wp)

#pragma unroll
    for (int mt = 0; mt < 4; mt++) {
        int r_lo = m0 + wm * 64 + mt * 16 + g;
#pragma unroll
        for (int nt = 0; nt < 4; nt++) {
            int col = n0 + wn * 32 + nt * 8 + 2 * t;
            float b0 = bias[col], b1 = bias[col + 1];
            float2 v0; v0.x = acc[mt][nt][0] + b0; v0.y = acc[mt][nt][1] + b1;
            *(float2*)&OUT[(size_t)r_lo * DM + col] = v0;
            float2 v1; v1.x = acc[mt][nt][2] + b0; v1.y = acc[mt][nt][3] + b1;
            *(float2*)&OUT[(size_t)(r_lo + 8) * DM + col] = v1;
        }
    }
}

// ---------------------------------------------------------------------------
// Fused flash attention, tf32 MMA, 2D WARP SPLIT (4M x 2N).
// Warp (wm2, wn2): S tile = q[wm2*32..+32) x keys[wn2*32..+32); PV tile =
// q[wm2*32..+32) x hd[wn2*32..+32) over ALL 64 keys (P shared via smem).
// K redundancy 8x->4x, V 8x->4x. Q streamed from gmem/L2 (pre-scaled,
// pair-permuted), 1-deep pipelined. P stored TRANSPOSED [key][q] stride 132:
// stores bank 8t+g, loads bank 4t+g — both conflict-free.
// Max-free softmax; per-warp partial row sums reduced once at epilogue.
// Smem: Ks 2*64*72 + Vs 2*64*72 + PT 64*132 words = 107520 B; 2 CTAs/SM.
// ---------------------------------------------------------------------------
#define KS_STRIDE 72
#define VS_STRIDE 72
#define PT_STRIDE 132
#define KS_OFF(b) ((b) * 64 * KS_STRIDE)
#define VS_OFF(b) (2 * 64 * KS_STRIDE + (b) * 64 * VS_STRIDE)
#define PT_OFF    (2 * 64 * KS_STRIDE + 2 * 64 * VS_STRIDE)
#define ATTN_SMEM_BYTES ((PT_OFF + 64 * PT_STRIDE) * 4)   // 107520

__global__ __launch_bounds__(256, 2) void attn_mma_kernel()
{
    extern __shared__ unsigned smem_u[];

    const int tid  = threadIdx.x;
    const int w    = tid >> 5;
    const int lane = tid & 31;
    const int g    = lane >> 2;
    const int t    = lane & 3;
    const int wm2  = w >> 1;          // q-tile (0..3)
    const int wn2  = w & 1;           // key/hd half (0..1)
    const int qbs  = wm2 * 32;        // warp q base within CTA tile
    const int kb   = wn2 * 32;        // warp key base within key tile
    const int hb   = wn2 * 32;        // warp hd base (PV)
    const int qc   = 2 * t;           // permuted col offset
    const int bh   = blockIdx.y;
    const int m0   = blockIdx.x << 7;

    const float* Qb = g_q + (size_t)bh * (SEQ * HD);
    const float* Kb = g_k + (size_t)bh * (SEQ * HD);
    const float* Vb = g_v + (size_t)bh * (SEQ * HD);

    // Q row pointers for this thread (4 rows: mt0 g, mt0 g+8, mt1 g, mt1 g+8)
    const float* qp0 = Qb + (size_t)(m0 + qbs + g)      * HD;
    const float* qp1 = Qb + (size_t)(m0 + qbs + g + 8)  * HD;
    const float* qp2 = Qb + (size_t)(m0 + qbs + g + 16) * HD;
    const float* qp3 = Qb + (size_t)(m0 + qbs + g + 24) * HD;

    // Prologue: async-load tile 0
#pragma unroll
    for (int i = 0; i < 4; i++) {
        int f   = i * 256 + tid;
        int key = f >> 4;
        int c4  = (f & 15) << 2;
        cp16(&smem_u[KS_OFF(0) + key * KS_STRIDE + c4], Kb + (size_t)key * HD + c4);
        cp16(&smem_u[VS_OFF(0) + key * VS_STRIDE + c4], Vb + (size_t)key * HD + c4);
    }
    asm volatile("cp.async.commit_group;");

    float o[2][4][4];
    float l[2][2] = {{0.f, 0.f}, {0.f, 0.f}};   // partial row sums (rows g, g+8 per mt)
#pragma unroll
    for (int mt = 0; mt < 2; mt++)
#pragma unroll
        for (int nt = 0; nt < 4; nt++)
#pragma unroll
            for (int c = 0; c < 4; c++) o[mt][nt][c] = 0.f;

    unsigned* PT = smem_u + PT_OFF;

    for (int it = 0; it < SEQ / 64; it++) {
        const int cur = it & 1;
        unsigned* Ks = smem_u + KS_OFF(cur);
        unsigned* Vs = smem_u + VS_OFF(cur);

        asm volatile("cp.async.wait_group 0;");
        __syncthreads();   // K/V resident; prior PV reads of PT complete

        if (it + 1 < SEQ / 64) {
            const int nxt = (it + 1) & 1;
            const size_t base = (size_t)(it + 1) * 64 * HD;
#pragma unroll
            for (int i = 0; i < 4; i++) {
                int f   = i * 256 + tid;
                int key = f >> 4;
                int c4  = (f & 15) << 2;
                cp16(&smem_u[KS_OFF(nxt) + key * KS_STRIDE + c4], Kb + base + (size_t)key * HD + c4);
                cp16(&smem_u[VS_OFF(nxt) + key * VS_STRIDE + c4], Vb + base + (size_t)key * HD + c4);
            }
            asm volatile("cp.async.commit_group;");
        }

        // ---- S = (Q/8) @ K^T  over warp's 32 keys, 1-deep Q pipeline ----
        float s[2][4][4];
#pragma unroll
        for (int mt = 0; mt < 2; mt++)
#pragma unroll
            for (int nt = 0; nt < 4; nt++)
#pragma unroll
                for (int c = 0; c < 4; c++) s[mt][nt][c] = 0.f;

        float2 q00 = ldg_f2v(qp0 + qc);
        float2 q01 = ldg_f2v(qp1 + qc);
        float2 q10 = ldg_f2v(qp2 + qc);
        float2 q11 = ldg_f2v(qp3 + qc);
#pragma unroll
        for (int kt = 0; kt < 8; kt++) {
            float2 c00 = q00, c01 = q01, c10 = q10, c11 = q11;
            if (kt < 7) {
                int off = (kt + 1) * 8 + qc;
                q00 = ldg_f2v(qp0 + off);
                q01 = ldg_f2v(qp1 + off);
                q10 = ldg_f2v(qp2 + off);
                q11 = ldg_f2v(qp3 + off);
            }
            unsigned a00 = __float_as_uint(c00.x), a01 = __float_as_uint(c01.x);
            unsigned a02 = __float_as_uint(c00.y), a03 = __float_as_uint(c01.y);
            unsigned a10 = __float_as_uint(c10.x), a11 = __float_as_uint(c11.x);
            unsigned a12 = __float_as_uint(c10.y), a13 = __float_as_uint(c11.y);
#pragma unroll
            for (int nt = 0; nt < 4; nt++) {
                uint2 bb = *(const uint2*)&Ks[(kb + nt * 8 + g) * KS_STRIDE + kt * 8 + qc];
                mma_tf32(s[0][nt][0], s[0][nt][1], s[0][nt][2], s[0][nt][3],
                         a00, a01, a02, a03, bb.x, bb.y);
                mma_tf32(s[1][nt][0], s[1][nt][1], s[1][nt][2], s[1][nt][3],
                         a10, a11, a12, a13, bb.x, bb.y);
            }
        }

        // ---- max-free exp + partial row sums ----
#pragma unroll
        for (int mt = 0; mt < 2; mt++)
#pragma unroll
            for (int nt = 0; nt < 4; nt++) {
                s[mt][nt][0] = __expf(s[mt][nt][0]);
                s[mt][nt][1] = __expf(s[mt][nt][1]);
                s[mt][nt][2] = __expf(s[mt][nt][2]);
                s[mt][nt][3] = __expf(s[mt][nt][3]);
                l[mt][0] += s[mt][nt][0] + s[mt][nt][1];
                l[mt][1] += s[mt][nt][2] + s[mt][nt][3];
            }

        // ---- P transposed store: PT[key][q], stride 132 (conflict-free) ----
#pragma unroll
        for (int mt = 0; mt < 2; mt++) {
            int q0i = qbs + mt * 16 + g;
#pragma unroll
            for (int nt = 0; nt < 4; nt++) {
                int k0 = kb + nt * 8 + 2 * t;
                PT[k0 * PT_STRIDE + q0i]           = f2tf(s[mt][nt][0]);
                PT[(k0 + 1) * PT_STRIDE + q0i]     = f2tf(s[mt][nt][1]);
                PT[k0 * PT_STRIDE + q0i + 8]       = f2tf(s[mt][nt][2]);
                PT[(k0 + 1) * PT_STRIDE + q0i + 8] = f2tf(s[mt][nt][3]);
            }
        }
        __syncthreads();   // P visible to partner warps before PV

        // ---- O += P @ V  over ALL 64 keys, warp's 32 hd cols ----
#pragma unroll
        for (int kt = 0; kt < 8; kt++) {
            int kr0 = kt * 8 + t;
            int kr1 = kt * 8 + t + 4;
            unsigned pa[2][4];
#pragma unroll
            for (int mt = 0; mt < 2; mt++) {
                int q0i = qbs + mt * 16 + g;
                pa[mt][0] = PT[kr0 * PT_STRIDE + q0i];
                pa[mt][1] = PT[kr0 * PT_STRIDE + q0i + 8];
                pa[mt][2] = PT[kr1 * PT_STRIDE + q0i];
                pa[mt][3] = PT[kr1 * PT_STRIDE + q0i + 8];
            }
#pragma unroll
            for (int nt = 0; nt < 4; nt++) {
                unsigned b0 = Vs[kr0 * VS_STRIDE + hb + nt * 8 + g];
                unsigned b1 = Vs[kr1 * VS_STRIDE + hb + nt * 8 + g];
                mma_tf32(o[0][nt][0], o[0][nt][1], o[0][nt][2], o[0][nt][3],
                         pa[0][0], pa[0][1], pa[0][2], pa[0][3], b0, b1);
                mma_tf32(o[1][nt][0], o[1][nt][1], o[1][nt][2], o[1][nt][3],
                         pa[1][0], pa[1][1], pa[1][2], pa[1][3], b0, b1);
            }
        }
    }

    // ---- Epilogue: cross-lane + cross-warp row-sum reduction, normalize ----
#pragma unroll
    for (int mt = 0; mt < 2; mt++)
#pragma unroll
        for (int r = 0; r < 2; r++) {
            l[mt][r] += __shfl_xor_sync(0xffffffffu, l[mt][r], 1);
            l[mt][r] += __shfl_xor_sync(0xffffffffu, l[mt][r], 2);
        }

    __syncthreads();                      // everyone past last PV; reuse smem
    float* rb = (float*)smem_u;           // rb[wn2*128 + row]
    if (t == 0) {
        rb[wn2 * 128 + qbs + g]      = l[0][0];
        rb[wn2 * 128 + qbs + g + 8]  = l[0][1];
        rb[wn2 * 128 + qbs + g + 16] = l[1][0];
        rb[wn2 * 128 + qbs + g + 24] = l[1][1];
    }
    __syncthreads();

    const int bat = bh / NH;
    const int h   = bh % NH;
#pragma unroll
    for (int mt = 0; mt < 2; mt++) {
        int r0 = qbs + mt * 16 + g;
        float inv0 = 1.0f / (rb[r0] + rb[128 + r0]);
        float inv1 = 1.0f / (rb[r0 + 8] + rb[128 + r0 + 8]);
        int gr0 = m0 + r0;
#pragma unroll
        for (int nt = 0; nt < 4; nt++) {
            int col = hb + nt * 8 + 2 * t;
            float2 v0;
            v0.x = __uint_as_float(f2tf(o[mt][nt][0] * inv0));
            v0.y = __uint_as_float(f2tf(o[mt][nt][1] * inv0));
            *(float2*)&g_ao[((size_t)(bat * SEQ + gr0) * NH + h) * HD + col] = v0;
            float2 v1;
            v1.x = __uint_as_float(f2tf(o[mt][nt][2] * inv1));
            v1.y = __uint_as_float(f2tf(o[mt][nt][3] * inv1));
            *(float2*)&g_ao[((size_t)(bat * SEQ + gr0 + 8) * NH + h) * HD + col] = v1;
        }
    }
}

// ---------------------------------------------------------------------------
extern "C" void kernel_launch(void* const* d_in, const int* in_sizes, int n_in,
                              void* d_out, int out_size)
{
    const float* x      = (const float*)d_in[0];
    const float* w_qkv  = (const float*)d_in[1];
    const float* b_qkv  = (const float*)d_in[2];
    const float* w_proj = (const float*)d_in[3];
    const float* b_proj = (const float*)d_in[4];
    float* out = (float*)d_out;

    cudaFuncSetAttribute(attn_mma_kernel,
                         cudaFuncAttributeMaxDynamicSharedMemorySize,
                         ATTN_SMEM_BYTES);
    cudaFuncSetAttribute(gemm_qkv_tf32,
                         cudaFuncAttributeMaxDynamicSharedMemorySize,
                         GEMM_SMEM_BYTES);
    cudaFuncSetAttribute(gemm_proj_tf32,
                         cudaFuncAttributeMaxDynamicSharedMemorySize,
                         GEMM_SMEM_BYTES);

    round_prepass<<<512, 256>>>(x, w_qkv, w_proj);

    dim3 g1(N1 / 128, MTOT / 128);     // (18, 64)
    gemm_qkv_tf32<<<g1, 256, GEMM_SMEM_BYTES>>>(b_qkv);

    dim3 ga(SEQ / 128, BATCH * NH);    // (16, 48)
    attn_mma_kernel<<<ga, 256, ATTN_SMEM_BYTES>>>();

    dim3 g2(DM / 128, MTOT / 128);     // (6, 64)
    gemm_proj_tf32<<<g2, 256, GEMM_SMEM_BYTES>>>(b_proj, out);
}

// round 8
// speedup vs baseline: 1.8051x; 1.8051x over previous
#include <cuda_runtime.h>
#include <cuda_fp16.h>
#include <math.h>

#define BATCH 4
#define SEQ   2048
#define DM    768
#define NH    12
#define HD    64
#define MTOT  (BATCH*SEQ)
#define N1    (3*DM)

// Scratch (static device arrays; no allocations allowed)
__device__ __half g_qh[BATCH*NH*SEQ*HD];  // [B,H,N,HD] fp16, PRE-SCALED by 1/8
__device__ __half g_kh[BATCH*NH*SEQ*HD];  // [B,H,N,HD] fp16
__device__ __half g_vh[BATCH*NH*SEQ*HD];  // [B,H,N,HD] fp16
__device__ float  g_ao[MTOT*DM];          // [B,N,H*HD] tf32-rounded fp32
__device__ float  g_xr[MTOT*DM];          // tf32-rounded x
__device__ float  g_wq[DM*N1];            // tf32-rounded w_qkv
__device__ float  g_wp[DM*DM];            // tf32-rounded w_proj

__device__ __forceinline__ unsigned f2tf(float f) {
    unsigned u;
    asm("cvt.rna.tf32.f32 %0, %1;" : "=r"(u) : "f"(f));
    return u;
}

__device__ __forceinline__ void mma_tf32(
    float &d0, float &d1, float &d2, float &d3,
    unsigned a0, unsigned a1, unsigned a2, unsigned a3,
    unsigned b0, unsigned b1)
{
    asm volatile(
        "mma.sync.aligned.m16n8k8.row.col.f32.tf32.tf32.f32 "
        "{%0,%1,%2,%3},{%4,%5,%6,%7},{%8,%9},{%0,%1,%2,%3};"
        : "+f"(d0), "+f"(d1), "+f"(d2), "+f"(d3)
        : "r"(a0), "r"(a1), "r"(a2), "r"(a3), "r"(b0), "r"(b1));
}

__device__ __forceinline__ void mma_f16(
    float &d0, float &d1, float &d2, float &d3,
    unsigned a0, unsigned a1, unsigned a2, unsigned a3,
    unsigned b0, unsigned b1)
{
    asm volatile(
        "mma.sync.aligned.m16n8k16.row.col.f32.f16.f16.f32 "
        "{%0,%1,%2,%3},{%4,%5,%6,%7},{%8,%9},{%0,%1,%2,%3};"
        : "+f"(d0), "+f"(d1), "+f"(d2), "+f"(d3)
        : "r"(a0), "r"(a1), "r"(a2), "r"(a3), "r"(b0), "r"(b1));
}

__device__ __forceinline__ void ldsm_x4(
    unsigned &d0, unsigned &d1, unsigned &d2, unsigned &d3, unsigned addr)
{
    asm volatile("ldmatrix.sync.aligned.m8n8.x4.shared.b16 {%0,%1,%2,%3}, [%4];"
                 : "=r"(d0), "=r"(d1), "=r"(d2), "=r"(d3) : "r"(addr));
}

__device__ __forceinline__ void ldsm_x4_t(
    unsigned &d0, unsigned &d1, unsigned &d2, unsigned &d3, unsigned addr)
{
    asm volatile("ldmatrix.sync.aligned.m8n8.x4.trans.shared.b16 {%0,%1,%2,%3}, [%4];"
                 : "=r"(d0), "=r"(d1), "=r"(d2), "=r"(d3) : "r"(addr));
}

__device__ __forceinline__ void cp16(void* smem, const void* g) {
    unsigned a = (unsigned)__cvta_generic_to_shared(smem);
    asm volatile("cp.async.cg.shared.global [%0], [%1], 16;" :: "r"(a), "l"(g));
}

__device__ __forceinline__ unsigned packh2(float lo, float hi) {
    __half2 h = __floats2half2_rn(lo, hi);
    return *(unsigned*)&h;
}

// ---------------------------------------------------------------------------
// Prepass: round x, w_qkv, w_proj to tf32 once.
// ---------------------------------------------------------------------------
__global__ void round_prepass(const float* __restrict__ x,
                              const float* __restrict__ wq,
                              const float* __restrict__ wp)
{
    const int i      = blockIdx.x * blockDim.x + threadIdx.x;
    const int stride = gridDim.x * blockDim.x;
#pragma unroll 1
    for (int j = i; j < MTOT * DM / 4; j += stride) {
        float4 v = ((const float4*)x)[j];
        uint4 u; u.x = f2tf(v.x); u.y = f2tf(v.y); u.z = f2tf(v.z); u.w = f2tf(v.w);
        ((uint4*)g_xr)[j] = u;
    }
#pragma unroll 1
    for (int j = i; j < DM * N1 / 4; j += stride) {
        float4 v = ((const float4*)wq)[j];
        uint4 u; u.x = f2tf(v.x); u.y = f2tf(v.y); u.z = f2tf(v.z); u.w = f2tf(v.w);
        ((uint4*)g_wq)[j] = u;
    }
#pragma unroll 1
    for (int j = i; j < DM * DM / 4; j += stride) {
        float4 v = ((const float4*)wp)[j];
        uint4 u; u.x = f2tf(v.x); u.y = f2tf(v.y); u.z = f2tf(v.z); u.w = f2tf(v.w);
        ((uint4*)g_wp)[j] = u;
    }
}

// ---------------------------------------------------------------------------
// tf32 MMA GEMM, cp.async double-buffered (unchanged mainloop).
// ---------------------------------------------------------------------------
#define AS_WORDS (128 * 36)
#define BS_WORDS (32 * 136)
#define GEMM_SMEM_BYTES (2 * (AS_WORDS + BS_WORDS) * 4)   // 71680

#define GEMM_PIPE_BODY(LDB, A_PTR, W_PTR)                                     \
    extern __shared__ unsigned dsm[];                                         \
    const int tid  = threadIdx.x;                                             \
    const int w    = tid >> 5;                                                \
    const int lane = tid & 31;                                                \
    const int g    = lane >> 2;                                               \
    const int t    = lane & 3;                                                \
    const int wm   = w & 1;                                                   \
    const int wn   = w >> 1;                                                  \
    const int m0   = blockIdx.y << 7;                                         \
    const int n0   = blockIdx.x << 7;                                         \
    float acc[4][4][4];                                                       \
    _Pragma("unroll")                                                         \
    for (int mt = 0; mt < 4; mt++)                                            \
        _Pragma("unroll")                                                     \
        for (int nt = 0; nt < 4; nt++)                                        \
            _Pragma("unroll")                                                 \
            for (int c = 0; c < 4; c++) acc[mt][nt][c] = 0.f;                 \
    {                                                                         \
        unsigned* As = dsm;                                                   \
        unsigned* Bs = dsm + 2 * AS_WORDS;                                    \
        _Pragma("unroll")                                                     \
        for (int i = 0; i < 4; i++) {                                         \
            int f = i * 256 + tid;                                            \
            int r = f >> 3;                                                   \
            int c = (f & 7) << 2;                                             \
            cp16(&As[r * 36 + c], (A_PTR) + (size_t)(m0 + r) * DM + c);       \
            int k = f >> 5;                                                   \
            int n = (f & 31) << 2;                                            \
            cp16(&Bs[k * 136 + n], (W_PTR) + (size_t)k * (LDB) + n0 + n);     \
        }                                                                     \
        asm volatile("cp.async.commit_group;");                               \
    }                                                                         \
    for (int it = 0; it < DM / 32; it++) {                                    \
        const int cur = it & 1;                                               \
        unsigned* As = dsm + cur * AS_WORDS;                                  \
        unsigned* Bs = dsm + 2 * AS_WORDS + cur * BS_WORDS;                   \
        asm volatile("cp.async.wait_group 0;");                               \
        __syncthreads();                                                      \
        if (it + 1 < DM / 32) {                                               \
            const int nxt = (it + 1) & 1;                                     \
            const int k0n = (it + 1) * 32;                                    \
            unsigned* An = dsm + nxt * AS_WORDS;                              \
            unsigned* Bn = dsm + 2 * AS_WORDS + nxt * BS_WORDS;               \
            _Pragma("unroll")                                                 \
            for (int i = 0; i < 4; i++) {                                     \
                int f = i * 256 + tid;                                        \
                int r = f >> 3;                                               \
                int c = (f & 7) << 2;                                         \
                cp16(&An[r * 36 + c], (A_PTR) + (size_t)(m0 + r) * DM + k0n + c); \
                int k = f >> 5;                                               \
                int n = (f & 31) << 2;                                        \
                cp16(&Bn[k * 136 + n], (W_PTR) + (size_t)(k0n + k) * (LDB) + n0 + n); \
            }                                                                 \
            asm volatile("cp.async.commit_group;");                           \
        }                                                                     \
        _Pragma("unroll")                                                     \
        for (int kk = 0; kk < 4; kk++) {                                      \
            unsigned a[4][4], b[4][2];                                        \
            _Pragma("unroll")                                                 \
            for (int mt = 0; mt < 4; mt++) {                                  \
                int row = wm * 64 + mt * 16;                                  \
                a[mt][0] = As[(row + g) * 36 + kk * 8 + t];                   \
                a[mt][1] = As[(row + 8 + g) * 36 + kk * 8 + t];               \
                a[mt][2] = As[(row + g) * 36 + kk * 8 + t + 4];               \
                a[mt][3] = As[(row + 8 + g) * 36 + kk * 8 + t + 4];           \
            }                                                                 \
            _Pragma("unroll")                                                 \
            for (int nt = 0; nt < 4; nt++) {                                  \
                int cn = wn * 32 + nt * 8 + g;                                \
                b[nt][0] = Bs[(kk * 8 + t) * 136 + cn];                       \
                b[nt][1] = Bs[(kk * 8 + t + 4) * 136 + cn];                   \
            }                                                                 \
            _Pragma("unroll")                                                 \
            for (int mt = 0; mt < 4; mt++)                                    \
                _Pragma("unroll")                                             \
                for (int nt = 0; nt < 4; nt++)                                \
                    mma_tf32(acc[mt][nt][0], acc[mt][nt][1],                  \
                             acc[mt][nt][2], acc[mt][nt][3],                  \
                             a[mt][0], a[mt][1], a[mt][2], a[mt][3],          \
                             b[nt][0], b[nt][1]);                             \
        }                                                                     \
        __syncthreads();                                                      \
    }

// GEMM1: qkv -> g_qh/g_kh/g_vh as fp16, natural [B,H,N,HD] layout.
// Q pre-scaled by 1/8 (exact pow-2).
__global__ __launch_bounds__(256, 2) void gemm_qkv_tf32(
    const float* __restrict__ bias)
{
    GEMM_PIPE_BODY(N1, g_xr, g_wq)

#pragma unroll
    for (int mt = 0; mt < 4; mt++) {
        int r_lo = m0 + wm * 64 + mt * 16 + g;
        int bat0 = r_lo >> 11,       n_0 = r_lo & (SEQ - 1);
        int bat1 = (r_lo + 8) >> 11, n_1 = (r_lo + 8) & (SEQ - 1);
#pragma unroll
        for (int nt = 0; nt < 4; nt++) {
            int col = n0 + wn * 32 + nt * 8 + 2 * t;
            int seg = col / DM;
            int cc  = col - seg * DM;
            int h   = cc >> 6;
            int hd  = cc & 63;
            float b0 = bias[col], b1 = bias[col + 1];
            __half* dst = (seg == 0) ? g_qh : (seg == 1) ? g_kh : g_vh;
            float sc    = (seg == 0) ? 0.125f : 1.0f;
            size_t base0 = ((size_t)(bat0 * NH + h) * SEQ + n_0) * HD + hd;
            size_t base1 = ((size_t)(bat1 * NH + h) * SEQ + n_1) * HD + hd;
            __half2 h0 = __floats2half2_rn((acc[mt][nt][0] + b0) * sc,
                                           (acc[mt][nt][1] + b1) * sc);
            *(__half2*)&dst[base0] = h0;
            __half2 h1 = __floats2half2_rn((acc[mt][nt][2] + b0) * sc,
                                           (acc[mt][nt][3] + b1) * sc);
            *(__half2*)&dst[base1] = h1;
        }
    }
}

// GEMM2: out = g_ao @ w_proj + b_proj (unchanged)
__global__ __launch_bounds__(256, 2) void gemm_proj_tf32(
    const float* __restrict__ bias, float* __restrict__ OUT)
{
    GEMM_PIPE_BODY(DM, g_ao, g_wp)

#pragma unroll
    for (int mt = 0; mt < 4; mt++) {
        int r_lo = m0 + wm * 64 + mt * 16 + g;
#pragma unroll
        for (int nt = 0; nt < 4; nt++) {
            int col = n0 + wn * 32 + nt * 8 + 2 * t;
            float b0 = bias[col], b1 = bias[col + 1];
            float2 v0; v0.x = acc[mt][nt][0] + b0; v0.y = acc[mt][nt][1] + b1;
            *(float2*)&OUT[(size_t)r_lo * DM + col] = v0;
            float2 v1; v1.x = acc[mt][nt][2] + b0; v1.y = acc[mt][nt][3] + b1;
            *(float2*)&OUT[(size_t)(r_lo + 8) * DM + col] = v1;
        }
    }
}

// ---------------------------------------------------------------------------
// Fused flash attention, fp16 MMA (m16n8k16), R6 structure:
// 8 warps M-split (warp = 16 q-rows), Bc=64, Q register-resident (16 regs),
// cp.async double-buffered K/V, max-free softmax.
// K b-frags via ldmatrix.x4 (non-trans), V via ldmatrix.x4.trans — no
// layout permutes, natural [key][hd] smem tiles, stride 72 halves (144 B:
// row stride ≡ 1 mod 8 in 16B groups -> conflict-free LDSM).
// P stays IN REGISTERS (d-frag cols == a-frag k-layout for k16).
// Smem: 4 buffers x 64x72 halves = 36864 B -> 2 CTAs/SM (reg-limited).
// ---------------------------------------------------------------------------
#define TSTR 72                         // halves per smem row
#define KS_HOFF(b) ((b) * 64 * TSTR)    // half offsets
#define VS_HOFF(b) (2 * 64 * TSTR + (b) * 64 * TSTR)
#define ATTN_SMEM_BYTES (4 * 64 * TSTR * 2)   // 36864

__global__ __launch_bounds__(256, 2) void attn_f16_kernel()
{
    extern __shared__ __half smem_h[];

    const int tid  = threadIdx.x;
    const int w    = tid >> 5;
    const int lane = tid & 31;
    const int g    = lane >> 2;
    const int t    = lane & 3;
    const int bh   = blockIdx.y;
    const int m0   = blockIdx.x << 7;

    const __half* Qb = g_qh + (size_t)bh * (SEQ * HD);
    const __half* Kb = g_kh + (size_t)bh * (SEQ * HD);
    const __half* Vb = g_vh + (size_t)bh * (SEQ * HD);

    // Q a-frags, register-resident: qa[ktg][0..3], ktg covers hd 16-groups
    unsigned qa[4][4];
    {
        const size_t r0 = (size_t)(m0 + w * 16 + g) * HD;
        const size_t r1 = r0 + 8 * HD;
#pragma unroll
        for (int ktg = 0; ktg < 4; ktg++) {
            qa[ktg][0] = *(const unsigned*)(Qb + r0 + ktg * 16 + 2 * t);
            qa[ktg][1] = *(const unsigned*)(Qb + r1 + ktg * 16 + 2 * t);
            qa[ktg][2] = *(const unsigned*)(Qb + r0 + ktg * 16 + 8 + 2 * t);
            qa[ktg][3] = *(const unsigned*)(Qb + r1 + ktg * 16 + 8 + 2 * t);
        }
    }

    const unsigned smb = (unsigned)__cvta_generic_to_shared(smem_h);
    // ldmatrix lane base offsets (bytes)
    const int lm = lane >> 3, lr = lane & 7;
    const unsigned cK = (unsigned)((((lm >> 1) * 8 + lr) * TSTR + (lm & 1) * 8) * 2);
    const unsigned cV = (unsigned)((((lm & 1) * 8 + lr) * TSTR + (lm >> 1) * 8) * 2);

    // Prologue: async-load tile 0 (K rows 64x128B, V rows 64x128B)
#pragma unroll
    for (int i = 0; i < 4; i++) {
        int f = i * 256 + tid;            // 0..1023 16B-chunks
        if (f < 512) {
            int key = f >> 3, c8 = (f & 7) * 8;
            cp16(&smem_h[KS_HOFF(0) + key * TSTR + c8], Kb + (size_t)key * HD + c8);
        } else {
            int f2 = f - 512;
            int key = f2 >> 3, c8 = (f2 & 7) * 8;
            cp16(&smem_h[VS_HOFF(0) + key * TSTR + c8], Vb + (size_t)key * HD + c8);
        }
    }
    asm volatile("cp.async.commit_group;");

    float o[8][4];
    float l0r = 0.f, l1r = 0.f;
#pragma unroll
    for (int nt = 0; nt < 8; nt++)
#pragma unroll
        for (int c = 0; c < 4; c++) o[nt][c] = 0.f;

    for (int it = 0; it < SEQ / 64; it++) {
        const int cur = it & 1;
        const unsigned KsB = smb + KS_HOFF(cur) * 2;
        const unsigned VsB = smb + VS_HOFF(cur) * 2;

        asm volatile("cp.async.wait_group 0;");
        __syncthreads();

        if (it + 1 < SEQ / 64) {
            const int nxt = (it + 1) & 1;
            const size_t base = (size_t)(it + 1) * 64 * HD;
#pragma unroll
            for (int i = 0; i < 4; i++) {
                int f = i * 256 + tid;
                if (f < 512) {
                    int key = f >> 3, c8 = (f & 7) * 8;
                    cp16(&smem_h[KS_HOFF(nxt) + key * TSTR + c8], Kb + base + (size_t)key * HD + c8);
                } else {
                    int f2 = f - 512;
                    int key = f2 >> 3, c8 = (f2 & 7) * 8;
                    cp16(&smem_h[VS_HOFF(nxt) + key * TSTR + c8], Vb + base + (size_t)key * HD + c8);
                }
            }
            asm volatile("cp.async.commit_group;");
        }

        // ---- S = (Q/8) @ K^T ----
        float s[8][4];
#pragma unroll
        for (int nt = 0; nt < 8; nt++)
#pragma unroll
            for (int c = 0; c < 4; c++) s[nt][c] = 0.f;

#pragma unroll
        for (int ktg = 0; ktg < 4; ktg++) {
#pragma unroll
            for (int np = 0; np < 4; np++) {
                unsigned b0, b1, b2, b3;
                ldsm_x4(b0, b1, b2, b3,
                        KsB + (unsigned)(np * 16 * TSTR * 2 + ktg * 32) + cK);
                mma_f16(s[2*np][0], s[2*np][1], s[2*np][2], s[2*np][3],
                        qa[ktg][0], qa[ktg][1], qa[ktg][2], qa[ktg][3], b0, b1);
                mma_f16(s[2*np+1][0], s[2*np+1][1], s[2*np+1][2], s[2*np+1][3],
                        qa[ktg][0], qa[ktg][1], qa[ktg][2], qa[ktg][3], b2, b3);
            }
        }

        // ---- max-free exp + row sums (fp32) ----
#pragma unroll
        for (int nt = 0; nt < 8; nt++) {
            s[nt][0] = __expf(s[nt][0]);
            s[nt][1] = __expf(s[nt][1]);
            s[nt][2] = __expf(s[nt][2]);
            s[nt][3] = __expf(s[nt][3]);
            l0r += s[nt][0] + s[nt][1];
            l1r += s[nt][2] + s[nt][3];
        }

        // ---- pack P to fp16 a-frags IN REGISTERS ----
        unsigned pa[4][4];
#pragma unroll
        for (int ktg = 0; ktg < 4; ktg++) {
            pa[ktg][0] = packh2(s[2*ktg][0],   s[2*ktg][1]);
            pa[ktg][1] = packh2(s[2*ktg][2],   s[2*ktg][3]);
            pa[ktg][2] = packh2(s[2*ktg+1][0], s[2*ktg+1][1]);
            pa[ktg][3] = packh2(s[2*ktg+1][2], s[2*ktg+1][3]);
        }

        // ---- O += P @ V ----
#pragma unroll
        for (int ktg = 0; ktg < 4; ktg++) {
#pragma unroll
            for (int np = 0; np < 4; np++) {
                unsigned b0, b1, b2, b3;
                ldsm_x4_t(b0, b1, b2, b3,
                          VsB + (unsigned)(ktg * 16 * TSTR * 2 + np * 32) + cV);
                mma_f16(o[2*np][0], o[2*np][1], o[2*np][2], o[2*np][3],
                        pa[ktg][0], pa[ktg][1], pa[ktg][2], pa[ktg][3], b0, b1);
                mma_f16(o[2*np+1][0], o[2*np+1][1], o[2*np+1][2], o[2*np+1][3],
                        pa[ktg][0], pa[ktg][1], pa[ktg][2], pa[ktg][3], b2, b3);
            }
        }
    }

    // ---- Epilogue: reduce row sums across 4 t-lanes, normalize, write ----
    l0r += __shfl_xor_sync(0xffffffffu, l0r, 1);
    l0r += __shfl_xor_sync(0xffffffffu, l0r, 2);
    l1r += __shfl_xor_sync(0xffffffffu, l1r, 1);
    l1r += __shfl_xor_sync(0xffffffffu, l1r, 2);

    const int bat = bh / NH;
    const int h   = bh % NH;
    const int n0g = m0 + w * 16 + g;
    const float inv0 = 1.0f / l0r;
    const float inv1 = 1.0f / l1r;
#pragma unroll
    for (int nt = 0; nt < 8; nt++) {
        int col = nt * 8 + 2 * t;
        float2 r0;
        r0.x = __uint_as_float(f2tf(o[nt][0] * inv0));
        r0.y = __uint_as_float(f2tf(o[nt][1] * inv0));
        *(float2*)&g_ao[((size_t)(bat * SEQ + n0g) * NH + h) * HD + col] = r0;
        float2 r1;
        r1.x = __uint_as_float(f2tf(o[nt][2] * inv1));
        r1.y = __uint_as_float(f2tf(o[nt][3] * inv1));
        *(float2*)&g_ao[((size_t)(bat * SEQ + n0g + 8) * NH + h) * HD + col] = r1;
    }
}

// ---------------------------------------------------------------------------
extern "C" void kernel_launch(void* const* d_in, const int* in_sizes, int n_in,
                              void* d_out, int out_size)
{
    const float* x      = (const float*)d_in[0];
    const float* w_qkv  = (const float*)d_in[1];
    const float* b_qkv  = (const float*)d_in[2];
    const float* w_proj = (const float*)d_in[3];
    const float* b_proj = (const float*)d_in[4];
    float* out = (float*)d_out;

    cudaFuncSetAttribute(gemm_qkv_tf32,
                         cudaFuncAttributeMaxDynamicSharedMemorySize,
                         GEMM_SMEM_BYTES);
    cudaFuncSetAttribute(gemm_proj_tf32,
                         cudaFuncAttributeMaxDynamicSharedMemorySize,
                         GEMM_SMEM_BYTES);

    round_prepass<<<512, 256>>>(x, w_qkv, w_proj);

    dim3 g1(N1 / 128, MTOT / 128);     // (18, 64)
    gemm_qkv_tf32<<<g1, 256, GEMM_SMEM_BYTES>>>(b_qkv);

    dim3 ga(SEQ / 128, BATCH * NH);    // (16, 48)
    attn_f16_kernel<<<ga, 256, ATTN_SMEM_BYTES>>>();

    dim3 g2(DM / 128, MTOT / 128);     // (6, 64)
    gemm_proj_tf32<<<g2, 256, GEMM_SMEM_BYTES>>>(b_proj, out);
}

// round 9
// speedup vs baseline: 2.5163x; 1.3940x over previous
#include <cuda_runtime.h>
#include <cuda_fp16.h>
#include <math.h>

#define BATCH 4
#define SEQ   2048
#define DM    768
#define NH    12
#define HD    64
#define MTOT  (BATCH*SEQ)
#define N1    (3*DM)

// Scratch (static device arrays; no allocations allowed)
__device__ __half g_qh [BATCH*NH*SEQ*HD]; // [B,H,N,HD] fp16, PRE-SCALED by 1/8
__device__ __half g_kh [BATCH*NH*SEQ*HD]; // [B,H,N,HD] fp16
__device__ __half g_vh [BATCH*NH*SEQ*HD]; // [B,H,N,HD] fp16
__device__ __half g_aoh[MTOT*DM];         // [B,N,H*HD] fp16 attention output
__device__ __half g_xh [MTOT*DM];         // fp16 x
__device__ __half g_wqh[DM*N1];           // fp16 w_qkv
__device__ __half g_wph[DM*DM];           // fp16 w_proj

__device__ __forceinline__ void mma_f16(
    float &d0, float &d1, float &d2, float &d3,
    unsigned a0, unsigned a1, unsigned a2, unsigned a3,
    unsigned b0, unsigned b1)
{
    asm volatile(
        "mma.sync.aligned.m16n8k16.row.col.f32.f16.f16.f32 "
        "{%0,%1,%2,%3},{%4,%5,%6,%7},{%8,%9},{%0,%1,%2,%3};"
        : "+f"(d0), "+f"(d1), "+f"(d2), "+f"(d3)
        : "r"(a0), "r"(a1), "r"(a2), "r"(a3), "r"(b0), "r"(b1));
}

__device__ __forceinline__ void ldsm_x4(
    unsigned &d0, unsigned &d1, unsigned &d2, unsigned &d3, unsigned addr)
{
    asm volatile("ldmatrix.sync.aligned.m8n8.x4.shared.b16 {%0,%1,%2,%3}, [%4];"
                 : "=r"(d0), "=r"(d1), "=r"(d2), "=r"(d3) : "r"(addr));
}

__device__ __forceinline__ void ldsm_x4_t(
    unsigned &d0, unsigned &d1, unsigned &d2, unsigned &d3, unsigned addr)
{
    asm volatile("ldmatrix.sync.aligned.m8n8.x4.trans.shared.b16 {%0,%1,%2,%3}, [%4];"
                 : "=r"(d0), "=r"(d1), "=r"(d2), "=r"(d3) : "r"(addr));
}

__device__ __forceinline__ void cp16(void* smem, const void* g) {
    unsigned a = (unsigned)__cvta_generic_to_shared(smem);
    asm volatile("cp.async.cg.shared.global [%0], [%1], 16;" :: "r"(a), "l"(g));
}

__device__ __forceinline__ unsigned packh2(float lo, float hi) {
    __half2 h = __floats2half2_rn(lo, hi);
    return *(unsigned*)&h;
}

// ---------------------------------------------------------------------------
// Prepass: convert x, w_qkv, w_proj to fp16 once.
// ---------------------------------------------------------------------------
__global__ void half_prepass(const float* __restrict__ x,
                             const float* __restrict__ wq,
                             const float* __restrict__ wp)
{
    const int i      = blockIdx.x * blockDim.x + threadIdx.x;
    const int stride = gridDim.x * blockDim.x;
#pragma unroll 1
    for (int j = i; j < MTOT * DM / 4; j += stride) {
        float4 v = ((const float4*)x)[j];
        uint2 u;
        u.x = packh2(v.x, v.y); u.y = packh2(v.z, v.w);
        ((uint2*)g_xh)[j] = u;
    }
#pragma unroll 1
    for (int j = i; j < DM * N1 / 4; j += stride) {
        float4 v = ((const float4*)wq)[j];
        uint2 u;
        u.x = packh2(v.x, v.y); u.y = packh2(v.z, v.w);
        ((uint2*)g_wqh)[j] = u;
    }
#pragma unroll 1
    for (int j = i; j < DM * DM / 4; j += stride) {
        float4 v = ((const float4*)wp)[j];
        uint2 u;
        u.x = packh2(v.x, v.y); u.y = packh2(v.z, v.w);
        ((uint2*)g_wph)[j] = u;
    }
}

// ---------------------------------------------------------------------------
// fp16 MMA GEMM (m16n8k16), cp.async double-buffered, ldmatrix fragments.
// 128x128 tile, BK=32, 8 warps (2x4), warp tile 64x32.
// As [m][k] stride 40 halves (80 B = 5x16B odd -> conflict-free LDSM).
// Bs [k][n] stride 136 halves (272 B = 17x16B odd -> conflict-free LDSM.T).
// d-frag layout == m16n8k8, so epilogues are unchanged from R8.
// Smem: 2*(128*40 + 32*136)*2 = 37888 B -> 2 CTAs/SM (reg-limited).
// ---------------------------------------------------------------------------
#define AHS 40
#define BHS 136
#define AS_HALVES (128 * AHS)   // 5120
#define BS_HALVES (32 * BHS)    // 4352
#define GEMM_SMEM_BYTES (2 * (AS_HALVES + BS_HALVES) * 2)   // 37888

#define GEMM_PIPE_BODY(LDB, A_PTR, W_PTR)                                     \
    extern __shared__ __half hsm[];                                           \
    const int tid  = threadIdx.x;                                             \
    const int w    = tid >> 5;                                                \
    const int lane = tid & 31;                                                \
    const int g    = lane >> 2;                                               \
    const int t    = lane & 3;                                                \
    const int wm   = w & 1;                                                   \
    const int wn   = w >> 1;                                                  \
    const int m0   = blockIdx.y << 7;                                         \
    const int n0   = blockIdx.x << 7;                                         \
    const int lm   = lane >> 3, lr = lane & 7;                                \
    const unsigned smb  = (unsigned)__cvta_generic_to_shared(hsm);            \
    const unsigned aoff = (unsigned)(((((lm & 1) * 8 + lr) * AHS) + (lm >> 1) * 8) * 2); \
    const unsigned boff = (unsigned)(((((lm & 1) * 8 + lr) * BHS) + (lm >> 1) * 8) * 2); \
    float acc[4][4][4];                                                       \
    _Pragma("unroll")                                                         \
    for (int mt = 0; mt < 4; mt++)                                            \
        _Pragma("unroll")                                                     \
        for (int nt = 0; nt < 4; nt++)                                        \
            _Pragma("unroll")                                                 \
            for (int c = 0; c < 4; c++) acc[mt][nt][c] = 0.f;                 \
    {                                                                         \
        __half* As = hsm;                                                     \
        __half* Bs = hsm + 2 * AS_HALVES;                                     \
        _Pragma("unroll")                                                     \
        for (int i = 0; i < 4; i++) {                                         \
            int f = i * 256 + tid;                                            \
            if (f < 512) {                                                    \
                int r = f >> 2, c8 = (f & 3) * 8;                             \
                cp16(&As[r * AHS + c8], (A_PTR) + (size_t)(m0 + r) * DM + c8); \
            } else {                                                          \
                int f2 = f - 512;                                             \
                int k = f2 >> 4, n8 = (f2 & 15) * 8;                          \
                cp16(&Bs[k * BHS + n8], (W_PTR) + (size_t)k * (LDB) + n0 + n8); \
            }                                                                 \
        }                                                                     \
        asm volatile("cp.async.commit_group;");                               \
    }                                                                         \
    for (int it = 0; it < DM / 32; it++) {                                    \
        const int cur = it & 1;                                               \
        const unsigned AsB = smb + (cur * AS_HALVES) * 2;                     \
        const unsigned BsB = smb + (2 * AS_HALVES + cur * BS_HALVES) * 2;     \
        asm volatile("cp.async.wait_group 0;");                               \
        __syncthreads();                                                      \
        if (it + 1 < DM / 32) {                                               \
            const int nxt = (it + 1) & 1;                                     \
            const int k0n = (it + 1) * 32;                                    \
            __half* An = hsm + nxt * AS_HALVES;                               \
            __half* Bn = hsm + 2 * AS_HALVES + nxt * BS_HALVES;               \
            _Pragma("unroll")                                                 \
            for (int i = 0; i < 4; i++) {                                     \
                int f = i * 256 + tid;                                        \
                if (f < 512) {                                                \
                    int r = f >> 2, c8 = (f & 3) * 8;                         \
                    cp16(&An[r * AHS + c8], (A_PTR) + (size_t)(m0 + r) * DM + k0n + c8); \
                } else {                                                      \
                    int f2 = f - 512;                                         \
                    int k = f2 >> 4, n8 = (f2 & 15) * 8;                      \
                    cp16(&Bn[k * BHS + n8], (W_PTR) + (size_t)(k0n + k) * (LDB) + n0 + n8); \
                }                                                             \
            }                                                                 \
            asm volatile("cp.async.commit_group;");                           \
        }                                                                     \
        _Pragma("unroll")                                                     \
        for (int ktg = 0; ktg < 2; ktg++) {                                   \
            unsigned a[4][4], b[2][4];                                        \
            _Pragma("unroll")                                                 \
            for (int mt = 0; mt < 4; mt++)                                    \
                ldsm_x4(a[mt][0], a[mt][1], a[mt][2], a[mt][3],               \
                        AsB + (unsigned)(((wm * 64 + mt * 16) * AHS + ktg * 16) * 2) + aoff); \
            _Pragma("unroll")                                                 \
            for (int np = 0; np < 2; np++)                                    \
                ldsm_x4_t(b[np][0], b[np][1], b[np][2], b[np][3],             \
                          BsB + (unsigned)((ktg * 16 * BHS + wn * 32 + np * 16) * 2) + boff); \
            _Pragma("unroll")                                                 \
            for (int mt = 0; mt < 4; mt++)                                    \
                _Pragma("unroll")                                             \
                for (int np = 0; np < 2; np++) {                              \
                    mma_f16(acc[mt][2*np][0], acc[mt][2*np][1],               \
                            acc[mt][2*np][2], acc[mt][2*np][3],               \
                            a[mt][0], a[mt][1], a[mt][2], a[mt][3],           \
                            b[np][0], b[np][1]);                              \
                    mma_f16(acc[mt][2*np+1][0], acc[mt][2*np+1][1],           \
                            acc[mt][2*np+1][2], acc[mt][2*np+1][3],           \
                            a[mt][0], a[mt][1], a[mt][2], a[mt][3],           \
                            b[np][2], b[np][3]);                              \
                }                                                             \
        }                                                                     \
        __syncthreads();                                                      \
    }

// GEMM1: qkv -> g_qh/g_kh/g_vh as fp16, natural [B,H,N,HD]; Q pre-scaled 1/8.
__global__ __launch_bounds__(256, 2) void gemm_qkv_f16(
    const float* __restrict__ bias)
{
    GEMM_PIPE_BODY(N1, g_xh, g_wqh)

#pragma unroll
    for (int mt = 0; mt < 4; mt++) {
        int r_lo = m0 + wm * 64 + mt * 16 + g;
        int bat0 = r_lo >> 11,       n_0 = r_lo & (SEQ - 1);
        int bat1 = (r_lo + 8) >> 11, n_1 = (r_lo + 8) & (SEQ - 1);
#pragma unroll
        for (int nt = 0; nt < 4; nt++) {
            int col = n0 + wn * 32 + nt * 8 + 2 * t;
            int seg = col / DM;
            int cc  = col - seg * DM;
            int h   = cc >> 6;
            int hd  = cc & 63;
            float b0 = bias[col], b1 = bias[col + 1];
            __half* dst = (seg == 0) ? g_qh : (seg == 1) ? g_kh : g_vh;
            float sc    = (seg == 0) ? 0.125f : 1.0f;
            size_t base0 = ((size_t)(bat0 * NH + h) * SEQ + n_0) * HD + hd;
            size_t base1 = ((size_t)(bat1 * NH + h) * SEQ + n_1) * HD + hd;
            __half2 h0 = __floats2half2_rn((acc[mt][nt][0] + b0) * sc,
                                           (acc[mt][nt][1] + b1) * sc);
            *(__half2*)&dst[base0] = h0;
            __half2 h1 = __floats2half2_rn((acc[mt][nt][2] + b0) * sc,
                                           (acc[mt][nt][3] + b1) * sc);
            *(__half2*)&dst[base1] = h1;
        }
    }
}

// GEMM2: out = g_aoh @ w_proj + b_proj (fp32 output)
__global__ __launch_bounds__(256, 2) void gemm_proj_f16(
    const float* __restrict__ bias, float* __restrict__ OUT)
{
    GEMM_PIPE_BODY(DM, g_aoh, g_wph)

#pragma unroll
    for (int mt = 0; mt < 4; mt++) {
        int r_lo = m0 + wm * 64 + mt * 16 + g;
#pragma unroll
        for (int nt = 0; nt < 4; nt++) {
            int col = n0 + wn * 32 + nt * 8 + 2 * t;
            float b0 = bias[col], b1 = bias[col + 1];
            float2 v0; v0.x = acc[mt][nt][0] + b0; v0.y = acc[mt][nt][1] + b1;
            *(float2*)&OUT[(size_t)r_lo * DM + col] = v0;
            float2 v1; v1.x = acc[mt][nt][2] + b0; v1.y = acc[mt][nt][3] + b1;
            *(float2*)&OUT[(size_t)(r_lo + 8) * DM + col] = v1;
        }
    }
}

// ---------------------------------------------------------------------------
// Fused flash attention, fp16 MMA (unchanged from R8 except fp16 g_aoh out).
// ---------------------------------------------------------------------------
#define TSTR 72
#define KS_HOFF(b) ((b) * 64 * TSTR)
#define VS_HOFF(b) (2 * 64 * TSTR + (b) * 64 * TSTR)
#define ATTN_SMEM_BYTES (4 * 64 * TSTR * 2)   // 36864

__global__ __launch_bounds__(256, 2) void attn_f16_kernel()
{
    extern __shared__ __half smem_h[];

    const int tid  = threadIdx.x;
    const int w    = tid >> 5;
    const int lane = tid & 31;
    const int g    = lane >> 2;
    const int t    = lane & 3;
    const int bh   = blockIdx.y;
    const int m0   = blockIdx.x << 7;

    const __half* Qb = g_qh + (size_t)bh * (SEQ * HD);
    const __half* Kb = g_kh + (size_t)bh * (SEQ * HD);
    const __half* Vb = g_vh + (size_t)bh * (SEQ * HD);

    unsigned qa[4][4];
    {
        const size_t r0 = (size_t)(m0 + w * 16 + g) * HD;
        const size_t r1 = r0 + 8 * HD;
#pragma unroll
        for (int ktg = 0; ktg < 4; ktg++) {
            qa[ktg][0] = *(const unsigned*)(Qb + r0 + ktg * 16 + 2 * t);
            qa[ktg][1] = *(const unsigned*)(Qb + r1 + ktg * 16 + 2 * t);
            qa[ktg][2] = *(const unsigned*)(Qb + r0 + ktg * 16 + 8 + 2 * t);
            qa[ktg][3] = *(const unsigned*)(Qb + r1 + ktg * 16 + 8 + 2 * t);
        }
    }

    const unsigned smb = (unsigned)__cvta_generic_to_shared(smem_h);
    const int lm = lane >> 3, lr = lane & 7;
    const unsigned cK = (unsigned)((((lm >> 1) * 8 + lr) * TSTR + (lm & 1) * 8) * 2);
    const unsigned cV = (unsigned)((((lm & 1) * 8 + lr) * TSTR + (lm >> 1) * 8) * 2);

#pragma unroll
    for (int i = 0; i < 4; i++) {
        int f = i * 256 + tid;
        if (f < 512) {
            int key = f >> 3, c8 = (f & 7) * 8;
            cp16(&smem_h[KS_HOFF(0) + key * TSTR + c8], Kb + (size_t)key * HD + c8);
        } else {
            int f2 = f - 512;
            int key = f2 >> 3, c8 = (f2 & 7) * 8;
            cp16(&smem_h[VS_HOFF(0) + key * TSTR + c8], Vb + (size_t)key * HD + c8);
        }
    }
    asm volatile("cp.async.commit_group;");

    float o[8][4];
    float l0r = 0.f, l1r = 0.f;
#pragma unroll
    for (int nt = 0; nt < 8; nt++)
#pragma unroll
        for (int c = 0; c < 4; c++) o[nt][c] = 0.f;

    for (int it = 0; it < SEQ / 64; it++) {
        const int cur = it & 1;
        const unsigned KsB = smb + KS_HOFF(cur) * 2;
        const unsigned VsB = smb + VS_HOFF(cur) * 2;

        asm volatile("cp.async.wait_group 0;");
        __syncthreads();

        if (it + 1 < SEQ / 64) {
            const int nxt = (it + 1) & 1;
            const size_t base = (size_t)(it + 1) * 64 * HD;
#pragma unroll
            for (int i = 0; i < 4; i++) {
                int f = i * 256 + tid;
                if (f < 512) {
                    int key = f >> 3, c8 = (f & 7) * 8;
                    cp16(&smem_h[KS_HOFF(nxt) + key * TSTR + c8], Kb + base + (size_t)key * HD + c8);
                } else {
                    int f2 = f - 512;
                    int key = f2 >> 3, c8 = (f2 & 7) * 8;
                    cp16(&smem_h[VS_HOFF(nxt) + key * TSTR + c8], Vb + base + (size_t)key * HD + c8);
                }
            }
            asm volatile("cp.async.commit_group;");
        }

        float s[8][4];
#pragma unroll
        for (int nt = 0; nt < 8; nt++)
#pragma unroll
            for (int c = 0; c < 4; c++) s[nt][c] = 0.f;

#pragma unroll
        for (int ktg = 0; ktg < 4; ktg++) {
#pragma unroll
            for (int np = 0; np < 4; np++) {
                unsigned b0, b1, b2, b3;
                ldsm_x4(b0, b1, b2, b3,
                        KsB + (unsigned)(np * 16 * TSTR * 2 + ktg * 32) + cK);
                mma_f16(s[2*np][0], s[2*np][1], s[2*np][2], s[2*np][3],
                        qa[ktg][0], qa[ktg][1], qa[ktg][2], qa[ktg][3], b0, b1);
                mma_f16(s[2*np+1][0], s[2*np+1][1], s[2*np+1][2], s[2*np+1][3],
                        qa[ktg][0], qa[ktg][1], qa[ktg][2], qa[ktg][3], b2, b3);
            }
        }

#pragma unroll
        for (int nt = 0; nt < 8; nt++) {
            s[nt][0] = __expf(s[nt][0]);
            s[nt][1] = __expf(s[nt][1]);
            s[nt][2] = __expf(s[nt][2]);
            s[nt][3] = __expf(s[nt][3]);
            l0r += s[nt][0] + s[nt][1];
            l1r += s[nt][2] + s[nt][3];
        }

        unsigned pa[4][4];
#pragma unroll
        for (int ktg = 0; ktg < 4; ktg++) {
            pa[ktg][0] = packh2(s[2*ktg][0],   s[2*ktg][1]);
            pa[ktg][1] = packh2(s[2*ktg][2],   s[2*ktg][3]);
            pa[ktg][2] = packh2(s[2*ktg+1][0], s[2*ktg+1][1]);
            pa[ktg][3] = packh2(s[2*ktg+1][2], s[2*ktg+1][3]);
        }

#pragma unroll
        for (int ktg = 0; ktg < 4; ktg++) {
#pragma unroll
            for (int np = 0; np < 4; np++) {
                unsigned b0, b1, b2, b3;
                ldsm_x4_t(b0, b1, b2, b3,
                          VsB + (unsigned)(ktg * 16 * TSTR * 2 + np * 32) + cV);
                mma_f16(o[2*np][0], o[2*np][1], o[2*np][2], o[2*np][3],
                        pa[ktg][0], pa[ktg][1], pa[ktg][2], pa[ktg][3], b0, b1);
                mma_f16(o[2*np+1][0], o[2*np+1][1], o[2*np+1][2], o[2*np+1][3],
                        pa[ktg][0], pa[ktg][1], pa[ktg][2], pa[ktg][3], b2, b3);
            }
        }
    }

    l0r += __shfl_xor_sync(0xffffffffu, l0r, 1);
    l0r += __shfl_xor_sync(0xffffffffu, l0r, 2);
    l1r += __shfl_xor_sync(0xffffffffu, l1r, 1);
    l1r += __shfl_xor_sync(0xffffffffu, l1r, 2);

    const int bat = bh / NH;
    const int h   = bh % NH;
    const int n0g = m0 + w * 16 + g;
    const float inv0 = 1.0f / l0r;
    const float inv1 = 1.0f / l1r;
#pragma unroll
    for (int nt = 0; nt < 8; nt++) {
        int col = nt * 8 + 2 * t;
        __half2 h0 = __floats2half2_rn(o[nt][0] * inv0, o[nt][1] * inv0);
        *(__half2*)&g_aoh[((size_t)(bat * SEQ + n0g) * NH + h) * HD + col] = h0;
        __half2 h1 = __floats2half2_rn(o[nt][2] * inv1, o[nt][3] * inv1);
        *(__half2*)&g_aoh[((size_t)(bat * SEQ + n0g + 8) * NH + h) * HD + col] = h1;
    }
}

// ---------------------------------------------------------------------------
extern "C" void kernel_launch(void* const* d_in, const int* in_sizes, int n_in,
                              void* d_out, int out_size)
{
    const float* x      = (const float*)d_in[0];
    const float* w_qkv  = (const float*)d_in[1];
    const float* b_qkv  = (const float*)d_in[2];
    const float* w_proj = (const float*)d_in[3];
    const float* b_proj = (const float*)d_in[4];
    float* out = (float*)d_out;

    half_prepass<<<512, 256>>>(x, w_qkv, w_proj);

    dim3 g1(N1 / 128, MTOT / 128);     // (18, 64)
    gemm_qkv_f16<<<g1, 256, GEMM_SMEM_BYTES>>>(b_qkv);

    dim3 ga(SEQ / 128, BATCH * NH);    // (16, 48)
    attn_f16_kernel<<<ga, 256, ATTN_SMEM_BYTES>>>();

    dim3 g2(DM / 128, MTOT / 128);     // (6, 64)
    gemm_proj_f16<<<g2, 256, GEMM_SMEM_BYTES>>>(b_proj, out);
}